// round 17
// baseline (speedup 1.0000x reference)
#include <cuda_runtime.h>
#include <cstdint>
#include <math.h>

// Problem dims
#define BSZ   2
#define QLEN  2048
#define DIM   1024
#define NH    16
#define HD    64
#define MTOT  (BSZ*QLEN)   // 4096

// Scratch (device globals). tf32 bit patterns. V is stored [b,h,d,q] (transposed).
__device__ uint32_t g_Q[BSZ*NH*QLEN*HD];
__device__ uint32_t g_K[BSZ*NH*QLEN*HD];
__device__ uint32_t g_V[BSZ*NH*QLEN*HD];
__device__ uint32_t g_C[MTOT*DIM];
__device__ uint32_t g_Xt[MTOT*DIM];
__device__ uint32_t g_WqkvT[3*DIM*DIM];
__device__ uint32_t g_WoT[DIM*DIM];

__device__ __forceinline__ uint32_t smem_u32(const void* p) {
    uint32_t a;
    asm("{ .reg .u64 t; cvta.to.shared.u64 t, %1; cvt.u32.u64 %0, t; }" : "=r"(a) : "l"(p));
    return a;
}
__device__ __forceinline__ void cp16(uint32_t saddr, const void* gaddr) {
    asm volatile("cp.async.cg.shared.global [%0], [%1], 16;" :: "r"(saddr), "l"(gaddr));
}
__device__ __forceinline__ void cp_commit() { asm volatile("cp.async.commit_group;"); }
template<int N>
__device__ __forceinline__ void cp_wait() { asm volatile("cp.async.wait_group %0;" :: "n"(N)); }

__device__ __forceinline__ uint32_t f2tf32(float f) {
    uint32_t u;
    asm("cvt.rna.tf32.f32 %0, %1;" : "=r"(u) : "f"(f));
    return u;
}
__device__ __forceinline__ void mma_tf32(float c[4],
    uint32_t a0, uint32_t a1, uint32_t a2, uint32_t a3, uint32_t b0, uint32_t b1)
{
    asm volatile(
        "mma.sync.aligned.m16n8k8.row.col.f32.tf32.tf32.f32 "
        "{%0,%1,%2,%3}, {%4,%5,%6,%7}, {%8,%9}, {%0,%1,%2,%3};"
        : "+f"(c[0]), "+f"(c[1]), "+f"(c[2]), "+f"(c[3])
        : "r"(a0), "r"(a1), "r"(a2), "r"(a3), "r"(b0), "r"(b1));
}
// ldmatrix x4 of b16 8x8 matrices; on tf32 data each matrix = 8 rows x 4 tf32.
__device__ __forceinline__ void ldsm4(uint32_t r[4], uint32_t addr) {
    asm volatile("ldmatrix.sync.aligned.m8n8.x4.shared.b16 {%0,%1,%2,%3}, [%4];"
        : "=r"(r[0]), "=r"(r[1]), "=r"(r[2]), "=r"(r[3]) : "r"(addr));
}

// ---------------------------------------------------------------------------
// elementwise fp32 -> tf32 bits
// ---------------------------------------------------------------------------
__global__ void to_tf32(const float* __restrict__ in, uint32_t* __restrict__ out)
{
    int idx = (blockIdx.x * 256 + threadIdx.x) * 4;
    float4 v = *(const float4*)(in + idx);
    uint4 u;
    u.x = f2tf32(v.x); u.y = f2tf32(v.y); u.z = f2tf32(v.z); u.w = f2tf32(v.w);
    *(uint4*)(out + idx) = u;
}

// ---------------------------------------------------------------------------
// Batched 32x32 transpose of 4 weight matrices, emits tf32 bits.
// ---------------------------------------------------------------------------
__global__ void transpose_w(const float* __restrict__ w0, const float* __restrict__ w1,
                            const float* __restrict__ w2, const float* __restrict__ w3,
                            uint32_t* __restrict__ qkvT, uint32_t* __restrict__ woT)
{
    __shared__ float tile[32][33];
    const int z = blockIdx.z;
    const float* in = (z == 0) ? w0 : (z == 1) ? w1 : (z == 2) ? w2 : w3;
    uint32_t* out = (z < 3) ? (qkvT + (size_t)z * DIM * DIM) : woT;

    int x = blockIdx.x * 32 + threadIdx.x;
    int y = blockIdx.y * 32 + threadIdx.y;
    #pragma unroll
    for (int i = 0; i < 32; i += 8)
        tile[threadIdx.y + i][threadIdx.x] = in[(size_t)(y + i) * DIM + x];
    __syncthreads();
    int x2 = blockIdx.y * 32 + threadIdx.x;
    int y2 = blockIdx.x * 32 + threadIdx.y;
    #pragma unroll
    for (int i = 0; i < 32; i += 8)
        out[(size_t)(y2 + i) * DIM + x2] = f2tf32(tile[threadIdx.x][threadIdx.y + i]);
}

// ---------------------------------------------------------------------------
// tf32 mma.sync GEMM core, ldmatrix fragment loads. BK=32, dynamic smem.
// MODE 0: fp32 row-major out. MODE 1: QKV fused; V written [b,h,d,q].
// ---------------------------------------------------------------------------
#define BM 128
#define BN 128
#define BK 32
#define PADK 36
#define GEMM_SMEM (2 * 2 * BM * PADK * 4 + BN * 4)

template<int MODE>
__global__ void __launch_bounds__(256) gemm_mma(
    const uint32_t* __restrict__ A, const uint32_t* __restrict__ Wt,
    const float* __restrict__ bias0, const float* __restrict__ bias1,
    const float* __restrict__ bias2,
    uint32_t* __restrict__ q_out, uint32_t* __restrict__ k_out,
    uint32_t* __restrict__ v_out, float* __restrict__ f_out, float qscale)
{
    extern __shared__ unsigned char dynsm[];
    uint32_t* As = (uint32_t*)dynsm;
    uint32_t* Bs = As + 2 * BM * PADK;
    float* s_bias = (float*)(Bs + 2 * BN * PADK);

    const int tid  = threadIdx.x;
    const int wid  = tid >> 5;
    const int lane = tid & 31;
    const int g    = lane >> 2;
    const int tg   = lane & 3;
    const int wr   = wid >> 2;
    const int wc   = wid & 3;
    const int br   = blockIdx.y * BM;
    const int bc   = blockIdx.x * BN;
    const int seg  = (MODE == 1) ? (bc >> 10) : 0;

    if (tid < BN) {
        const float* bp = (MODE == 0) ? bias0
                         : (seg == 0) ? bias0 : (seg == 1) ? bias1 : bias2;
        s_bias[tid] = bp[(MODE == 1 ? (bc & 1023) : bc) + tid];
    }

    const uint32_t aRow = (lane & 7) + ((lane >> 3) & 1) * 8;
    const uint32_t aCol = (lane >> 4) * 4;
    const uint32_t aoffB = (aRow * PADK + aCol) * 4u;
    const uint32_t bRow = (lane & 7) + (lane >> 4) * 8;
    const uint32_t bCol = ((lane >> 3) & 1) * 4;
    const uint32_t boffB = (bRow * PADK + bCol) * 4u;

    uint32_t aAddr[4], bAddr[4];
    const uint32_t* aPtr[4];
    const uint32_t* bPtr[4];
    const uint32_t aBase = smem_u32(As);
    const uint32_t bBase = smem_u32(Bs);
    #pragma unroll
    for (int i = 0; i < 4; i++) {
        int u = i * 256 + tid;
        int row = u >> 3;
        int k4  = (u & 7) * 4;
        aAddr[i] = aBase + (uint32_t)(row * PADK + k4) * 4u;
        bAddr[i] = bBase + (uint32_t)(row * PADK + k4) * 4u;
        aPtr[i]  = A  + (size_t)(br + row) * DIM + k4;
        bPtr[i]  = Wt + (size_t)(bc + row) * DIM + k4;
    }
    const uint32_t stageA = (uint32_t)(BM * PADK) * 4u;
    const uint32_t stageB = (uint32_t)(BN * PADK) * 4u;

    float acc[4][4][4];
    #pragma unroll
    for (int mt = 0; mt < 4; mt++)
        #pragma unroll
        for (int nt = 0; nt < 4; nt++)
            #pragma unroll
            for (int i = 0; i < 4; i++) acc[mt][nt][i] = 0.0f;

    #pragma unroll
    for (int i = 0; i < 4; i++) { cp16(aAddr[i], aPtr[i]); cp16(bAddr[i], bPtr[i]); }
    cp_commit();

    const int KT = DIM / BK;
    for (int kt = 0; kt < KT; kt++) {
        const int buf = kt & 1;
        if (kt + 1 < KT) {
            const int nb = (kt + 1) & 1;
            const int k0 = (kt + 1) * BK;
            #pragma unroll
            for (int i = 0; i < 4; i++) {
                cp16(aAddr[i] + nb * stageA, aPtr[i] + k0);
                cp16(bAddr[i] + nb * stageB, bPtr[i] + k0);
            }
            cp_commit();
            cp_wait<1>();
        } else {
            cp_wait<0>();
        }
        __syncthreads();

        const uint32_t AbB = aBase + buf * stageA + aoffB;
        const uint32_t BbB = bBase + buf * stageB + boffB;
        #pragma unroll
        for (int ks = 0; ks < BK; ks += 8) {
            uint32_t af[4][4];
            #pragma unroll
            for (int mt = 0; mt < 4; mt++)
                ldsm4(af[mt], AbB + (uint32_t)(((wr * 64 + mt * 16) * PADK + ks) * 4));
            uint32_t bf[4][2];
            #pragma unroll
            for (int np = 0; np < 2; np++) {
                uint32_t t[4];
                ldsm4(t, BbB + (uint32_t)(((wc * 32 + np * 16) * PADK + ks) * 4));
                bf[np * 2][0] = t[0]; bf[np * 2][1] = t[1];
                bf[np * 2 + 1][0] = t[2]; bf[np * 2 + 1][1] = t[3];
            }
            #pragma unroll
            for (int mt = 0; mt < 4; mt++)
                #pragma unroll
                for (int nt = 0; nt < 4; nt++)
                    mma_tf32(acc[mt][nt], af[mt][0], af[mt][1], af[mt][2], af[mt][3],
                             bf[nt][0], bf[nt][1]);
        }
        __syncthreads();
    }

    const float scale = (MODE == 1 && seg == 0) ? qscale : 1.0f;
    uint32_t* hs_out = (seg == 0) ? q_out : (seg == 1) ? k_out : v_out;
    #pragma unroll
    for (int mt = 0; mt < 4; mt++) {
        #pragma unroll
        for (int nt = 0; nt < 4; nt++) {
            const int nl = wc * 32 + nt * 8 + tg * 2;
            const float b0 = s_bias[nl], b1 = s_bias[nl + 1];
            #pragma unroll
            for (int half = 0; half < 2; half++) {
                const int m = br + wr * 64 + mt * 16 + g + half * 8;
                float vx = (acc[mt][nt][half * 2 + 0] + b0) * scale;
                float vy = (acc[mt][nt][half * 2 + 1] + b1) * scale;
                if (MODE == 0) {
                    const int n = bc + nl;
                    float2 v; v.x = vx; v.y = vy;
                    *(float2*)(f_out + (size_t)m * DIM + n) = v;
                } else {
                    const int nloc = (bc & 1023) + nl;
                    const int bb = m >> 11, q = m & 2047, h = nloc >> 6, d = nloc & 63;
                    if (seg == 2) {
                        uint32_t* vb = hs_out + ((size_t)(bb * NH + h) * HD) * QLEN;
                        vb[(size_t)d * QLEN + q]       = f2tf32(vx);
                        vb[(size_t)(d + 1) * QLEN + q] = f2tf32(vy);
                    } else {
                        uint2 u; u.x = f2tf32(vx); u.y = f2tf32(vy);
                        *(uint2*)(hs_out + (((size_t)bb * NH + h) * QLEN + q) * HD + d) = u;
                    }
                }
            }
        }
    }
}

// ---------------------------------------------------------------------------
// Tensor-core flash attention; 64-row Q tile, 3 CTAs/SM.
// Register softmax + staggered K/V prefetch (K(0) prologue; V(t) during S;
// K(t+1) during softmax/PV). Warp tile 16x32.
// ---------------------------------------------------------------------------
#define PA 68
#define PV 68
#define QT 64
#define ATTN_SMEM ((4*64*PA + 64 + 64 + 2*64 + 2*64 + 64) * 4)

__global__ void __launch_bounds__(256, 3) attn_mma(
    const uint32_t* __restrict__ Q, const uint32_t* __restrict__ K,
    const uint32_t* __restrict__ V, const float* __restrict__ mask,
    uint32_t* __restrict__ ctx)
{
    extern __shared__ unsigned char smraw[];
    uint32_t* Qs  = (uint32_t*)smraw;                         // 64 x PA
    float*    Ssh = (float*)(smraw + (64*PA)*4);              // 64 x PA (P bits)
    uint32_t* Ks  = (uint32_t*)(smraw + (2*64*PA)*4);         // 64 x PA
    uint32_t* Vs  = (uint32_t*)(smraw + (3*64*PA)*4);         // 64 x PV (d-major)
    float*    msh  = (float*)(Vs + 64*PV);                    // 64
    float*    lsh  = msh + 64;                                // 64
    float*    wmax = lsh + 64;                                // 2 x 64
    float*    wsum = wmax + 128;                              // 2 x 64
    float*    madd = wsum + 128;                              // 64

    const int tid  = threadIdx.x;
    const int wid  = tid >> 5;
    const int lane = tid & 31;
    const int g    = lane >> 2;
    const int tg   = lane & 3;
    const int wr   = wid >> 1;          // 0..3 -> 16-row slab
    const int wc   = wid & 1;           // 0..1 -> 32-col slab
    const int rb   = wr * 16;

    const int bh = blockIdx.x;
    const int b  = bh >> 4;
    const int h  = bh & 15;
    const int q0 = blockIdx.y * QT;

    const uint32_t* Qh = Q + (size_t)bh * QLEN * HD;
    const uint32_t* Kh = K + (size_t)bh * QLEN * HD;
    const uint32_t* Vh = V + (size_t)bh * QLEN * HD;   // [d][q]
    const float* mb = mask + (size_t)b * QLEN;

    const uint32_t qsBase = smem_u32(Qs);
    const uint32_t ssBase = smem_u32(Ssh);
    const uint32_t ksBase = smem_u32(Ks);
    const uint32_t vsBase = smem_u32(Vs);

    const uint32_t aRow = (lane & 7) + ((lane >> 3) & 1) * 8;
    const uint32_t aCol = (lane >> 4) * 4;
    const uint32_t aoffA = (aRow * PA + aCol) * 4u;
    const uint32_t bRow = (lane & 7) + (lane >> 4) * 8;
    const uint32_t bCol = ((lane >> 3) & 1) * 4;
    const uint32_t boffK = (bRow * PA + bCol) * 4u;
    const uint32_t boffV = (bRow * PV + bCol) * 4u;

    // per-thread cp.async slots (4 rows x 16-cols-of-4)
    const int cpR  = tid >> 4;
    const int cpC4 = (tid & 15) * 4;

    // prologue: issue K(0)
    #pragma unroll
    for (int i = 0; i < 4; i++) {
        int r = cpR + i * 16;
        cp16(ksBase + (uint32_t)(r * PA + cpC4) * 4u, Kh + (size_t)r * HD + cpC4);
    }
    cp_commit();

    // stage Q (bit copy): 64x64 = 1024 uint4 -> 4 per thread
    #pragma unroll
    for (int i = 0; i < 4; i++) {
        int idx = tid + i * 256;
        int r = idx >> 4, c4 = (idx & 15) * 4;
        *(uint4*)(&Qs[r * PA + c4]) = *(const uint4*)(Qh + (size_t)(q0 + r) * HD + c4);
    }
    if (tid < 64) { msh[tid] = -1e30f; lsh[tid] = 0.0f; }

    float o[4][4];
    #pragma unroll
    for (int nt = 0; nt < 4; nt++)
        #pragma unroll
        for (int i = 0; i < 4; i++) o[nt][i] = 0.0f;

    for (int t = 0; t < QLEN / 64; t++) {
        const int kk0 = t * 64;
        __syncthreads();   // A: prev PV done (Vs free); msh/lsh updates visible

        // issue V(t): overlaps S-phase MMAs
        #pragma unroll
        for (int i = 0; i < 4; i++) {
            int r = cpR + i * 16;
            cp16(vsBase + (uint32_t)(r * PV + cpC4) * 4u, Vh + (size_t)r * QLEN + kk0 + cpC4);
        }
        cp_commit();
        if (tid < 64) madd[tid] = -1e30f * (1.0f - mb[kk0 + tid]);

        cp_wait<1>();      // K(t) done; V(t) still in flight
        __syncthreads();   // B

        float2 ma[4];
        #pragma unroll
        for (int nt = 0; nt < 4; nt++)
            ma[nt] = *(float2*)(&madd[wc * 32 + nt * 8 + tg * 2]);

        // S = Q @ K^T (warp: rows rb..rb+15, keys wc*32..+31)
        float sacc[4][4];
        #pragma unroll
        for (int nt = 0; nt < 4; nt++)
            #pragma unroll
            for (int i = 0; i < 4; i++) sacc[nt][i] = 0.0f;

        #pragma unroll
        for (int ks = 0; ks < 8; ks++) {
            const int k = ks * 8;
            uint32_t af[4];
            ldsm4(af, qsBase + aoffA + (uint32_t)((rb * PA + k) * 4));
            uint32_t bf[4][2];
            #pragma unroll
            for (int np = 0; np < 2; np++) {
                uint32_t tt[4];
                ldsm4(tt, ksBase + boffK + (uint32_t)(((wc * 32 + np * 16) * PA + k) * 4));
                bf[np * 2][0] = tt[0]; bf[np * 2][1] = tt[1];
                bf[np * 2 + 1][0] = tt[2]; bf[np * 2 + 1][1] = tt[3];
            }
            #pragma unroll
            for (int nt = 0; nt < 4; nt++)
                mma_tf32(sacc[nt], af[0], af[1], af[2], af[3], bf[nt][0], bf[nt][1]);
        }

        // add mask in registers
        #pragma unroll
        for (int nt = 0; nt < 4; nt++) {
            sacc[nt][0] += ma[nt].x; sacc[nt][1] += ma[nt].y;
            sacc[nt][2] += ma[nt].x; sacc[nt][3] += ma[nt].y;
        }

        // row max: lane-local -> quad shfl -> half-exchange via smem
        #pragma unroll
        for (int hh = 0; hh < 2; hh++) {
            float mx = fmaxf(sacc[0][2*hh], sacc[0][2*hh+1]);
            #pragma unroll
            for (int nt = 1; nt < 4; nt++)
                mx = fmaxf(mx, fmaxf(sacc[nt][2*hh], sacc[nt][2*hh+1]));
            mx = fmaxf(mx, __shfl_xor_sync(0xffffffffu, mx, 1));
            mx = fmaxf(mx, __shfl_xor_sync(0xffffffffu, mx, 2));
            if (tg == 0) wmax[wc * 64 + rb + g + 8 * hh] = mx;
        }
        __syncthreads();   // C: wmax visible; S-phase Ks reads done

        // issue K(t+1): overlaps softmax + PV (clamped on last tile)
        {
            const int kknext = (t + 1 < QLEN / 64) ? (kk0 + 64) : kk0;
            #pragma unroll
            for (int i = 0; i < 4; i++) {
                int r = cpR + i * 16;
                cp16(ksBase + (uint32_t)(r * PA + cpC4) * 4u,
                     Kh + (size_t)(kknext + r) * HD + cpC4);
            }
            cp_commit();
        }

        float mnew[2], alpha[2];
        #pragma unroll
        for (int hh = 0; hh < 2; hh++) {
            const int r = rb + g + 8 * hh;
            const float mo = msh[r];
            const float mn = fmaxf(mo, fmaxf(wmax[r], wmax[64 + r]));
            mnew[hh]  = mn;
            alpha[hh] = __expf(mo - mn);
            float s = 0.0f;
            #pragma unroll
            for (int nt = 0; nt < 4; nt++) {
                float p0 = __expf(sacc[nt][2*hh]     - mn);
                float p1 = __expf(sacc[nt][2*hh + 1] - mn);
                sacc[nt][2*hh]     = __uint_as_float(f2tf32(p0));
                sacc[nt][2*hh + 1] = __uint_as_float(f2tf32(p1));
                s += p0 + p1;
            }
            s += __shfl_xor_sync(0xffffffffu, s, 1);
            s += __shfl_xor_sync(0xffffffffu, s, 2);
            if (tg == 0) wsum[wc * 64 + r] = s;
        }

        // write P (tf32 bits)
        #pragma unroll
        for (int hh = 0; hh < 2; hh++) {
            const int r = rb + g + 8 * hh;
            #pragma unroll
            for (int nt = 0; nt < 4; nt++) {
                float2 pv;
                pv.x = sacc[nt][2*hh];
                pv.y = sacc[nt][2*hh + 1];
                *(float2*)(&Ssh[r * PA + wc * 32 + nt * 8 + tg * 2]) = pv;
            }
        }

        cp_wait<1>();      // V(t) done; K(t+1) still in flight
        __syncthreads();   // D: P + wsum + Vs visible

        if (wc == 0 && tg == 0) {
            #pragma unroll
            for (int hh = 0; hh < 2; hh++) {
                const int r = rb + g + 8 * hh;
                lsh[r] = lsh[r] * alpha[hh] + wsum[r] + wsum[64 + r];
                msh[r] = mnew[hh];
            }
        }

        // rescale O, then O += P @ V
        #pragma unroll
        for (int nt = 0; nt < 4; nt++) {
            o[nt][0] *= alpha[0]; o[nt][1] *= alpha[0];
            o[nt][2] *= alpha[1]; o[nt][3] *= alpha[1];
        }
        #pragma unroll
        for (int ks = 0; ks < 8; ks++) {
            const int k = ks * 8;
            uint32_t af[4];
            ldsm4(af, ssBase + aoffA + (uint32_t)((rb * PA + k) * 4));
            uint32_t bf[4][2];
            #pragma unroll
            for (int np = 0; np < 2; np++) {
                uint32_t tt[4];
                ldsm4(tt, vsBase + boffV + (uint32_t)(((wc * 32 + np * 16) * PV + k) * 4));
                bf[np * 2][0] = tt[0]; bf[np * 2][1] = tt[1];
                bf[np * 2 + 1][0] = tt[2]; bf[np * 2 + 1][1] = tt[3];
            }
            #pragma unroll
            for (int nt = 0; nt < 4; nt++)
                mma_tf32(o[nt], af[0], af[1], af[2], af[3], bf[nt][0], bf[nt][1]);
        }
    }
    __syncthreads();   // final lsh updates visible

    // write context [b, q, h*HD + d] as tf32 bits
    {
        const int r0 = rb + g;
        const float inv_lo = 1.0f / lsh[r0];
        const float inv_hi = 1.0f / lsh[r0 + 8];
        #pragma unroll
        for (int nt = 0; nt < 4; nt++) {
            const int d = h * HD + wc * 32 + nt * 8 + tg * 2;
            const int m0 = q0 + r0;
            uint2 u0; u0.x = f2tf32(o[nt][0] * inv_lo); u0.y = f2tf32(o[nt][1] * inv_lo);
            *(uint2*)(&ctx[((size_t)(b * QLEN + m0)) * DIM + d]) = u0;
            uint2 u1; u1.x = f2tf32(o[nt][2] * inv_hi); u1.y = f2tf32(o[nt][3] * inv_hi);
            *(uint2*)(&ctx[((size_t)(b * QLEN + m0 + 8)) * DIM + d]) = u1;
        }
    }
}

// ---------------------------------------------------------------------------
extern "C" void kernel_launch(void* const* d_in, const int* in_sizes, int n_in,
                              void* d_out, int out_size)
{
    const float* x    = (const float*)d_in[0];
    const float* mask = (const float*)d_in[1];
    const float* Wq   = (const float*)d_in[2];
    const float* bq   = (const float*)d_in[3];
    const float* Wk   = (const float*)d_in[4];
    const float* bk   = (const float*)d_in[5];
    const float* Wv   = (const float*)d_in[6];
    const float* bv   = (const float*)d_in[7];
    const float* Wo   = (const float*)d_in[8];
    const float* bo   = (const float*)d_in[9];
    float* out = (float*)d_out;

    uint32_t *Qp, *Kp, *Vp, *Cp, *Xt, *WqkvT, *WoT;
    cudaGetSymbolAddress((void**)&Qp, g_Q);
    cudaGetSymbolAddress((void**)&Kp, g_K);
    cudaGetSymbolAddress((void**)&Vp, g_V);
    cudaGetSymbolAddress((void**)&Cp, g_C);
    cudaGetSymbolAddress((void**)&Xt, g_Xt);
    cudaGetSymbolAddress((void**)&WqkvT, g_WqkvT);
    cudaGetSymbolAddress((void**)&WoT, g_WoT);

    to_tf32<<<MTOT * DIM / 1024, 256>>>(x, Xt);
    transpose_w<<<dim3(32, 32, 4), dim3(32, 8)>>>(Wq, Wk, Wv, Wo, WqkvT, WoT);

    const float qscale = 1.0f / sqrtf((float)HD);

    cudaFuncSetAttribute(gemm_mma<1>, cudaFuncAttributeMaxDynamicSharedMemorySize, GEMM_SMEM);
    cudaFuncSetAttribute(gemm_mma<0>, cudaFuncAttributeMaxDynamicSharedMemorySize, GEMM_SMEM);

    gemm_mma<1><<<dim3(3 * DIM / 128, MTOT / 128), 256, GEMM_SMEM>>>(
        Xt, WqkvT, bq, bk, bv, Qp, Kp, Vp, nullptr, qscale);

    cudaFuncSetAttribute(attn_mma, cudaFuncAttributeMaxDynamicSharedMemorySize, ATTN_SMEM);
    attn_mma<<<dim3(BSZ * NH, QLEN / QT), 256, ATTN_SMEM>>>(Qp, Kp, Vp, mask, Cp);

    gemm_mma<0><<<dim3(DIM / 128, MTOT / 128), 256, GEMM_SMEM>>>(
        Cp, WoT, bo, nullptr, nullptr, nullptr, nullptr, nullptr, out, 1.0f);
}